// round 10
// baseline (speedup 1.0000x reference)
#include <cuda_runtime.h>
#include <cuda_fp16.h>
#include <cstdint>

#define DI __device__ __forceinline__

static const int QL  = 128;
static const int VL  = 2048;
static const int HID = 1024;

// ---------------------------------------------------------------------------
// Scratch (device globals; no runtime allocation allowed). fp16 operands.
// ---------------------------------------------------------------------------
__device__ uint16_t s_Wq_h[1048576];                    // Wq hi
__device__ uint16_t s_Wv_h[1048576];                    // Wv hi
__device__ uint16_t g_qh_h[4194304];                    // qp result [n][q][d]
__device__ uint16_t g_vh_h[67108864];                   // vp result [n][v][d]
__device__ uint16_t g_vhT_h[67108864];                  // vp result [n][d][v]
__device__ float g_A0[128], g_A1[128], g_A2[128], g_Cc[128];
__device__ float g_mp[524288], g_lp[524288];            // softmax partials [n][16][128]

// ---------------------------------------------------------------------------
DI uint32_t smem_u32(const void* p) {
    uint32_t a;
    asm("{ .reg .u64 t; cvta.to.shared.u64 t, %1; cvt.u32.u64 %0, t; }" : "=r"(a) : "l"(p));
    return a;
}

DI uint32_t sp2h(float a, float b, uint32_t& lo) {
    __half2 h = __floats2half2_rn(a, b);
    float2 f = __half22float2(h);
    __half2 l = __floats2half2_rn(a - f.x, b - f.y);
    lo = *(uint32_t*)&l;
    return *(uint32_t*)&h;
}
DI uint32_t pk2h(float a, float b) {
    __half2 h = __floats2half2_rn(a, b);
    return *(uint32_t*)&h;
}

DI void ldm4(uint32_t* r, uint32_t a) {
    asm volatile("ldmatrix.sync.aligned.m8n8.x4.shared.b16 {%0,%1,%2,%3}, [%4];"
        : "=r"(r[0]), "=r"(r[1]), "=r"(r[2]), "=r"(r[3]) : "r"(a));
}

DI void mma16816(float* d, const uint32_t* a, uint32_t b0, uint32_t b1) {
    asm volatile("mma.sync.aligned.m16n8k16.row.col.f32.f16.f16.f32 "
        "{%0,%1,%2,%3},{%4,%5,%6,%7},{%8,%9},{%0,%1,%2,%3};"
        : "+f"(d[0]), "+f"(d[1]), "+f"(d[2]), "+f"(d[3])
        : "r"(a[0]), "r"(a[1]), "r"(a[2]), "r"(a[3]), "r"(b0), "r"(b1));
}

DI void cp16(uint32_t dst, const void* src) {
    asm volatile("cp.async.cg.shared.global [%0], [%1], 16;" :: "r"(dst), "l"(src));
}
#define CP_COMMIT() asm volatile("cp.async.commit_group;" ::: "memory")
#define CP_WAIT2()  asm volatile("cp.async.wait_group 2;"  ::: "memory")

static const int TILE_B = 10240;

// ---------------------------------------------------------------------------
// Unified GEMM, 128x128 tile, 3-stage pipeline, 2 CTAs/SM.
// MODE 0: qp = q@Wq^T + bq       -> g_qh_h         grid(8, 32)  A reg fp32,2-pass
// MODE 1: vp = v@Wv^T + bias+loc -> g_vh_h,g_vhT_h grid(8, 512) A reg fp32,1-pass
// MODE 2: score: e=exp(s-m_tile) -> attn + (m,l) partials  grid(16,256) 1-pass
// MODE 3: out = P@vh, P=e*corr   -> out; attn = P (normalized)  grid(256) 1-pass
// ---------------------------------------------------------------------------
template <int MODE>
__global__ void __launch_bounds__(256, 2)
mma_gemm(const float* __restrict__ Ain, const float* __restrict__ biasv,
         const float* __restrict__ la, float* __restrict__ dsto)
{
    extern __shared__ char sm[];
    const uint32_t smb = smem_u32(sm);
    const int t = threadIdx.x, lane = t & 31, w = t >> 5;
    const int wm0 = (w & 3) * 32, wn0 = (w >> 2) * 64;

    constexpr int  K    = (MODE < 2) ? HID : (MODE == 2 ? 128 : VL);
    constexpr int  NC   = K / 32;
    constexpr int  NPA  = (MODE == 0) ? 2 : 1;
    constexpr int  NT   = (MODE == 0) ? 3 : 2;
    constexpr int  BUF  = NT * TILE_B;
    constexpr bool REGA = (MODE != 2);
    constexpr uint32_t BOFF = (uint32_t)(NT - 1) * TILE_B;

    const uint16_t *Ah16 = nullptr, *Bh = nullptr;
    const float* Afp = nullptr;
    float* attw = nullptr;
    const float* mpRow = nullptr;
    float m_st = 0.f, li_st = 0.f;
    int lda = 0, ldb = 0;
    if (MODE == 0) {
        Afp = Ain + (size_t)blockIdx.y * 128 * HID;
        Bh  = s_Wq_h + (size_t)blockIdx.x * 128 * HID; lda = ldb = HID;
    } else if (MODE == 1) {
        Afp = Ain + (size_t)blockIdx.y * 128 * HID;
        Bh  = s_Wv_h + (size_t)blockIdx.x * 128 * HID; lda = ldb = HID;
    } else if (MODE == 2) {
        Ah16 = g_qh_h + (size_t)blockIdx.y * QL * 128;
        Bh   = g_vh_h + (size_t)blockIdx.y * VL * 128 + (size_t)blockIdx.x * 128 * 128;
        lda = ldb = 128;
    } else {
        Afp  = Ain + (size_t)blockIdx.x * QL * VL;
        attw = (float*)Ain + (size_t)blockIdx.x * QL * VL;
        Bh   = g_vhT_h + (size_t)blockIdx.x * 128 * VL; lda = VL; ldb = VL;
        // merge softmax partials for this loader thread's row
        const int myrow = t >> 1;
        mpRow = g_mp + (size_t)blockIdx.x * 2048 + myrow;
        const float* lp = g_lp + (size_t)blockIdx.x * 2048 + myrow;
        float m = -1e30f;
#pragma unroll
        for (int i = 0; i < 16; i++) m = fmaxf(m, mpRow[i * 128]);
        float l = 0.f;
#pragma unroll
        for (int i = 0; i < 16; i++) l += lp[i * 128] * __expf(mpRow[i * 128] - m);
        m_st = m; li_st = 1.0f / l;
    }

    float acc[2][8][4];
#pragma unroll
    for (int i = 0; i < 2; i++)
#pragma unroll
        for (int j = 0; j < 8; j++)
#pragma unroll
            for (int k = 0; k < 4; k++) acc[i][j][k] = 0.f;

    // ---- cp.async loaders ----
    auto cp_chunk = [&](int buf, int c) {   // MODE 2: A + B tiles
        uint32_t sb = smb + buf * BUF;
#pragma unroll
        for (int i = 0; i < 4; i++) {
            int idx = t + 256 * i;
            int tile = idx >> 9, r = (idx >> 2) & 127, s = idx & 3;
            const uint16_t* base = tile ? Bh : Ah16;
            int ld = tile ? ldb : lda;
            uint32_t doff = tile ? TILE_B : 0u;
            cp16(sb + doff + r * 80 + s * 16, base + (size_t)r * ld + c * 32 + s * 8);
        }
    };
    auto cp_chunk_b = [&](int buf, int c) { // REGA modes: B only
        uint32_t sb = smb + buf * BUF + BOFF;
#pragma unroll
        for (int i = 0; i < 2; i++) {
            int idx = t + 256 * i;
            int r = (idx >> 2) & 127, s = idx & 3;
            cp16(sb + r * 80 + s * 16, Bh + (size_t)r * ldb + c * 32 + s * 8);
        }
    };

    auto compute = [&](uint32_t sbuf) {
#pragma unroll
        for (int ks = 0; ks < 2; ks++) {
            const uint32_t rowsel = (uint32_t)(lane & 15) * 80
                                  + (uint32_t)((lane >> 4) + ks * 2) * 16;
            uint32_t aH[2][4], bH[4][4];
#pragma unroll
            for (int mt = 0; mt < 2; mt++)
                ldm4(aH[mt], sbuf + (uint32_t)(wm0 + mt * 16) * 80 + rowsel);
#pragma unroll
            for (int g = 0; g < 4; g++)
                ldm4(bH[g], sbuf + BOFF + (uint32_t)(wn0 + g * 16) * 80 + rowsel);
#pragma unroll
            for (int mt = 0; mt < 2; mt++)
#pragma unroll
                for (int g = 0; g < 4; g++) {
                    mma16816(acc[mt][2 * g],     aH[mt], bH[g][0], bH[g][2]);
                    mma16816(acc[mt][2 * g + 1], aH[mt], bH[g][1], bH[g][3]);
                }
            if (NPA == 2) {
#pragma unroll
                for (int mt = 0; mt < 2; mt++)
                    ldm4(aH[mt], sbuf + TILE_B + (uint32_t)(wm0 + mt * 16) * 80 + rowsel);
#pragma unroll
                for (int mt = 0; mt < 2; mt++)
#pragma unroll
                    for (int g = 0; g < 4; g++) {
                        mma16816(acc[mt][2 * g],     aH[mt], bH[g][0], bH[g][2]);
                        mma16816(acc[mt][2 * g + 1], aH[mt], bH[g][1], bH[g][3]);
                    }
            }
        }
    };

    // ---- register A path (modes 0/1/3): fp32 -> fp16 convert in-loader ----
    float4 arg[4];
    const float* apA = REGA ? Afp + (size_t)(t >> 1) * lda + (t & 1) * 16 : nullptr;
    float* awA = (MODE == 3) ? attw + (size_t)(t >> 1) * VL + (t & 1) * 16 : nullptr;
    const uint32_t aoff = (t >> 1) * 80 + (t & 1) * 32;

    auto LD_A = [&](int c) {
#pragma unroll
        for (int j = 0; j < 4; j++) arg[j] = *(const float4*)(apA + (size_t)c * 32 + j * 4);
    };
    auto STS_A = [&](int buf, int ch) {
        char* bb = sm + buf * BUF;
        if (MODE == 0) {
            uint4 H, L;
            H.x = sp2h(arg[0].x, arg[0].y, L.x); H.y = sp2h(arg[0].z, arg[0].w, L.y);
            H.z = sp2h(arg[1].x, arg[1].y, L.z); H.w = sp2h(arg[1].z, arg[1].w, L.w);
            *(uint4*)(bb + aoff) = H; *(uint4*)(bb + TILE_B + aoff) = L;
            H.x = sp2h(arg[2].x, arg[2].y, L.x); H.y = sp2h(arg[2].z, arg[2].w, L.y);
            H.z = sp2h(arg[3].x, arg[3].y, L.z); H.w = sp2h(arg[3].z, arg[3].w, L.w);
            *(uint4*)(bb + aoff + 16) = H; *(uint4*)(bb + TILE_B + aoff + 16) = L;
        } else if (MODE == 1) {
            uint4 H;
            H.x = pk2h(arg[0].x, arg[0].y); H.y = pk2h(arg[0].z, arg[0].w);
            H.z = pk2h(arg[1].x, arg[1].y); H.w = pk2h(arg[1].z, arg[1].w);
            *(uint4*)(bb + aoff) = H;
            H.x = pk2h(arg[2].x, arg[2].y); H.y = pk2h(arg[2].z, arg[2].w);
            H.z = pk2h(arg[3].x, arg[3].y); H.w = pk2h(arg[3].z, arg[3].w);
            *(uint4*)(bb + aoff + 16) = H;
        } else { // MODE 3: e -> P = e*corr; write normalized attn; fp16 hi
            float cr = __expf(mpRow[(ch >> 2) * 128] - m_st) * li_st;
            float* aw = awA + (size_t)ch * 32;
            float4 P[4];
#pragma unroll
            for (int j = 0; j < 4; j++) {
                P[j].x = arg[j].x * cr; P[j].y = arg[j].y * cr;
                P[j].z = arg[j].z * cr; P[j].w = arg[j].w * cr;
                *(float4*)(aw + j * 4) = P[j];
            }
            uint4 H;
            H.x = pk2h(P[0].x, P[0].y); H.y = pk2h(P[0].z, P[0].w);
            H.z = pk2h(P[1].x, P[1].y); H.w = pk2h(P[1].z, P[1].w);
            *(uint4*)(bb + aoff) = H;
            H.x = pk2h(P[2].x, P[2].y); H.y = pk2h(P[2].z, P[2].w);
            H.z = pk2h(P[3].x, P[3].y); H.w = pk2h(P[3].z, P[3].w);
            *(uint4*)(bb + aoff + 16) = H;
        }
    };

    // ---- prologue ----
    if (REGA) {
        LD_A(0); STS_A(0, 0);
        LD_A(1); STS_A(1, 1);
        LD_A(2); STS_A(2, 2);
        LD_A(3);
        cp_chunk_b(0, 0); CP_COMMIT();
        cp_chunk_b(1, 1); CP_COMMIT();
        cp_chunk_b(2, 2); CP_COMMIT();
    } else {
        cp_chunk(0, 0); CP_COMMIT();
        cp_chunk(1, 1); CP_COMMIT();
        cp_chunk(2, 2); CP_COMMIT();
    }

    int buf = 0;
    for (int c = 0; c < NC; c++) {
        CP_WAIT2();
        __syncthreads();
        compute(smb + buf * BUF);
        __syncthreads();
        if (c + 3 < NC) {
            if (REGA) { STS_A(buf, c + 3); cp_chunk_b(buf, c + 3); }
            else      cp_chunk(buf, c + 3);
        }
        CP_COMMIT();
        if (REGA && c + 4 < NC) LD_A(c + 4);
        buf = (buf == 2) ? 0 : buf + 1;
    }

    // ------------------------- epilogues -------------------------
    if (MODE == 2) {
        // attn <- e = exp(s*sc - m_tile); partials (m_tile, l_tile) -> g_mp/g_lp
        float* pm = (float*)(sm + 34048);   // [2][128] half-maxes
        float* mM = pm + 256;               // [128] merged tile max
        float* pl = mM + 128;               // [2][128] half l-sums
        const float sc = 0.08838834764831845f;
#pragma unroll
        for (int mt = 0; mt < 2; mt++)
#pragma unroll
            for (int h2 = 0; h2 < 2; h2++) {
                const int row = wm0 + mt * 16 + (lane >> 2) + h2 * 8;
                float mx = -1e30f;
#pragma unroll
                for (int nt = 0; nt < 8; nt++)
                    mx = fmaxf(mx, fmaxf(acc[mt][nt][2 * h2], acc[mt][nt][2 * h2 + 1]));
                mx *= sc;
                mx = fmaxf(mx, __shfl_xor_sync(~0u, mx, 1));
                mx = fmaxf(mx, __shfl_xor_sync(~0u, mx, 2));
                if ((lane & 3) == 0) pm[(w >> 2) * 128 + row] = mx;
            }
        __syncthreads();
        if (t < 128) mM[t] = fmaxf(pm[t], pm[128 + t]);
        __syncthreads();
#pragma unroll
        for (int mt = 0; mt < 2; mt++)
#pragma unroll
            for (int h2 = 0; h2 < 2; h2++) {
                const int row = wm0 + mt * 16 + (lane >> 2) + h2 * 8;
                const float mm = mM[row];
                float* ad = dsto + ((size_t)blockIdx.y * QL + row) * VL + blockIdx.x * 128;
                float l = 0.f;
#pragma unroll
                for (int nt = 0; nt < 8; nt++) {
                    const int col = wn0 + nt * 8 + 2 * (lane & 3);
                    float e0 = __expf(acc[mt][nt][2 * h2]     * sc - mm);
                    float e1 = __expf(acc[mt][nt][2 * h2 + 1] * sc - mm);
                    *(float2*)(ad + col) = make_float2(e0, e1);
                    l += e0 + e1;
                }
                l += __shfl_xor_sync(~0u, l, 1);
                l += __shfl_xor_sync(~0u, l, 2);
                if ((lane & 3) == 0) pl[(w >> 2) * 128 + row] = l;
            }
        __syncthreads();
        if (t < 128) {
            size_t o = ((size_t)blockIdx.y * 16 + blockIdx.x) * 128 + t;
            g_mp[o] = mM[t];
            g_lp[o] = pl[t] + pl[128 + t];
        }
        return;
    }

    float* vec = (float*)(sm + 34048);
    if (MODE == 0) {
        if (t < 128) vec[t] = biasv[blockIdx.x * 128 + t];
    }
    if (MODE == 1) {
        if (t < 128) {
            vec[t]       = biasv[blockIdx.x * 128 + t] + g_Cc[t];
            vec[128 + t] = g_A0[t];
            vec[256 + t] = g_A1[t];
            vec[384 + t] = g_A2[t];
        }
        const int b = blockIdx.y >> 4, h = blockIdx.x;
        const int vpos0 = (blockIdx.y & 15) * 128;
        const float* lar = la + (size_t)(b * 8 + h) * VL;
        if (t < 130) {
            int g = vpos0 - 1 + t;
            vec[512 + t] = (g >= 0 && g < VL) ? lar[g] : 0.f;
        }
    }
    __syncthreads();

#pragma unroll
    for (int mt = 0; mt < 2; mt++) {
#pragma unroll
        for (int h2 = 0; h2 < 2; h2++) {
            const int row = wm0 + mt * 16 + (lane >> 2) + h2 * 8;
            size_t obase = 0;
            float* dst = nullptr;
            float lm1 = 0.f, l0 = 0.f, lp1 = 0.f;
            if (MODE == 0) {
                obase = (((size_t)(blockIdx.x * 32 + blockIdx.y)) * QL + row) * 128;
            } else if (MODE == 1) {
                int b = blockIdx.y >> 4, h = blockIdx.x;
                int vpos0 = (blockIdx.y & 15) * 128;
                lm1 = vec[512 + row]; l0 = vec[513 + row]; lp1 = vec[514 + row];
                obase = (((size_t)(h * 32 + b)) * VL + vpos0 + row) * 128;
            } else {
                int h = blockIdx.x >> 5, b = blockIdx.x & 31;
                dst = dsto + ((size_t)(b * QL + row)) * HID + h * 128;
            }
#pragma unroll
            for (int nt = 0; nt < 8; nt++) {
                const int col = wn0 + nt * 8 + 2 * (lane & 3);
                float x = acc[mt][nt][2 * h2];
                float y = acc[mt][nt][2 * h2 + 1];
                if (MODE == 0) {
                    x += vec[col]; y += vec[col + 1];
                    *(uint32_t*)&g_qh_h[obase + col] = pk2h(x, y);
                } else if (MODE == 1) {
                    x += vec[col]     + vec[128 + col]     * lm1 + vec[256 + col]     * l0 + vec[384 + col]     * lp1;
                    y += vec[col + 1] + vec[128 + col + 1] * lm1 + vec[256 + col + 1] * l0 + vec[384 + col + 1] * lp1;
                    uint32_t hi = pk2h(x, y);
                    *(uint32_t*)&g_vh_h[obase + col] = hi;
                    *(uint32_t*)(sm + (row * 65 + (col >> 1)) * 4) = hi;
                } else {
                    *(float2*)(dst + col) = make_float2(x, y);
                }
            }
        }
    }

    if (MODE == 1) {
        __syncthreads();
        const int b = blockIdx.y >> 4, h = blockIdx.x;
        const int vpos0 = (blockIdx.y & 15) * 128;
        const int d = t >> 1, vh2 = t & 1;
        size_t ob = (((size_t)(h * 32 + b)) * 128 + d) * VL + vpos0 + vh2 * 64;
#pragma unroll
        for (int blk = 0; blk < 8; blk++) {
            uint16_t e[8];
#pragma unroll
            for (int j = 0; j < 8; j++) {
                int v = vh2 * 64 + blk * 8 + j;
                e[j] = *(uint16_t*)(sm + (v * 65 + (d >> 1)) * 4 + (d & 1) * 2);
            }
            uint4 o;
            o.x = (uint32_t)e[0] | ((uint32_t)e[1] << 16);
            o.y = (uint32_t)e[2] | ((uint32_t)e[3] << 16);
            o.z = (uint32_t)e[4] | ((uint32_t)e[5] << 16);
            o.w = (uint32_t)e[6] | ((uint32_t)e[7] << 16);
            *(uint4*)&g_vhT_h[ob + blk * 8] = o;
        }
    }
}

// ---------------------------------------------------------------------------
DI void split_body(const float4* __restrict__ in, uint16_t* oh, int n4) {
    int i = blockIdx.x * 256 + threadIdx.x;
    if (i >= n4) return;
    float4 x = in[i];
    uint2 H;
    H.x = pk2h(x.x, x.y); H.y = pk2h(x.z, x.w);
    *(uint2*)&oh[(size_t)i * 4] = H;
}
__global__ void split_wq_k(const float4* in) { split_body(in, s_Wq_h, 262144); }
__global__ void split_wv_k(const float4* in) { split_body(in, s_Wv_h, 262144); }

// ---------------------------------------------------------------------------
__global__ void prep_kernel(const float* __restrict__ conv_w,
                            const float* __restrict__ conv_b,
                            const float* __restrict__ Wloc)
{
    int d = threadIdx.x;
    float a0 = 0.f, a1 = 0.f, a2 = 0.f, c = 0.f;
#pragma unroll
    for (int cc = 0; cc < 10; cc++) {
        float wl = Wloc[d * 10 + cc];
        a0 += wl * conv_w[cc * 3 + 0];
        a1 += wl * conv_w[cc * 3 + 1];
        a2 += wl * conv_w[cc * 3 + 2];
        c  += wl * conv_b[cc];
    }
    g_A0[d] = a0; g_A1[d] = a1; g_A2[d] = a2; g_Cc[d] = c;
}

// ---------------------------------------------------------------------------
extern "C" void kernel_launch(void* const* d_in, const int* in_sizes, int n_in,
                              void* d_out, int out_size)
{
    const float* q         = (const float*)d_in[0];
    const float* v         = (const float*)d_in[1];
    const float* last_attn = (const float*)d_in[2];
    const float* conv_w    = (const float*)d_in[3];
    const float* conv_b    = (const float*)d_in[4];
    const float* Wq        = (const float*)d_in[5];
    const float* bq        = (const float*)d_in[6];
    const float* Wv        = (const float*)d_in[7];
    const float* Wloc      = (const float*)d_in[8];
    const float* bias      = (const float*)d_in[9];

    float* out  = (float*)d_out;
    float* attn = out + 4194304;

    const int SM3 = 3 * 3 * TILE_B;   // 92160 (mode 0)
    const int SM2 = 3 * 2 * TILE_B;   // 61440 (modes 1/2/3)

    static bool attr_done = false;
    if (!attr_done) {
        cudaFuncSetAttribute(mma_gemm<0>, cudaFuncAttributeMaxDynamicSharedMemorySize, SM3);
        cudaFuncSetAttribute(mma_gemm<1>, cudaFuncAttributeMaxDynamicSharedMemorySize, SM2);
        cudaFuncSetAttribute(mma_gemm<2>, cudaFuncAttributeMaxDynamicSharedMemorySize, SM2);
        cudaFuncSetAttribute(mma_gemm<3>, cudaFuncAttributeMaxDynamicSharedMemorySize, SM2);
        attr_done = true;
    }

    prep_kernel<<<1, 128>>>(conv_w, conv_b, Wloc);
    split_wq_k<<<1024, 256>>>((const float4*)Wq);
    split_wv_k<<<1024, 256>>>((const float4*)Wv);

    mma_gemm<0><<<dim3(8, 32),   256, SM3>>>(q,    bq,   nullptr,   nullptr);
    mma_gemm<1><<<dim3(8, 512),  256, SM2>>>(v,    bias, last_attn, nullptr);
    mma_gemm<2><<<dim3(16, 256), 256, SM2>>>(nullptr, nullptr, nullptr, attn);
    mma_gemm<3><<<256, 256, SM2>>>(attn, nullptr, nullptr, out);
}

// round 11
// speedup vs baseline: 1.1089x; 1.1089x over previous
#include <cuda_runtime.h>
#include <cuda_fp16.h>
#include <cstdint>

#define DI __device__ __forceinline__

static const int QL  = 128;
static const int VL  = 2048;
static const int HID = 1024;

// ---------------------------------------------------------------------------
// Scratch (device globals; no runtime allocation allowed). fp16 operands.
// ---------------------------------------------------------------------------
__device__ uint16_t s_q_h[4194304], s_q_l[4194304];     // split q (2-pass A)
__device__ uint16_t s_v_h[67108864];                    // v hi (1-pass A)
__device__ uint16_t s_Wq_h[1048576];                    // Wq hi
__device__ uint16_t s_Wv_h[1048576];                    // Wv hi
__device__ uint16_t g_qh_h[4194304];                    // qp result [n][q][d]
__device__ uint16_t g_vh_h[67108864];                   // vp result [n][v][d]
__device__ uint16_t g_vhT_h[67108864];                  // vp result [n][d][v]
__device__ float g_A0[128], g_A1[128], g_A2[128], g_Cc[128];
__device__ float g_mp[524288], g_lp[524288];            // softmax partials [n][16][128]

// ---------------------------------------------------------------------------
DI uint32_t smem_u32(const void* p) {
    uint32_t a;
    asm("{ .reg .u64 t; cvta.to.shared.u64 t, %1; cvt.u32.u64 %0, t; }" : "=r"(a) : "l"(p));
    return a;
}

DI uint32_t sp2h(float a, float b, uint32_t& lo) {
    __half2 h = __floats2half2_rn(a, b);
    float2 f = __half22float2(h);
    __half2 l = __floats2half2_rn(a - f.x, b - f.y);
    lo = *(uint32_t*)&l;
    return *(uint32_t*)&h;
}
DI uint32_t pk2h(float a, float b) {
    __half2 h = __floats2half2_rn(a, b);
    return *(uint32_t*)&h;
}

DI void ldm4(uint32_t* r, uint32_t a) {
    asm volatile("ldmatrix.sync.aligned.m8n8.x4.shared.b16 {%0,%1,%2,%3}, [%4];"
        : "=r"(r[0]), "=r"(r[1]), "=r"(r[2]), "=r"(r[3]) : "r"(a));
}

DI void mma16816(float* d, const uint32_t* a, uint32_t b0, uint32_t b1) {
    asm volatile("mma.sync.aligned.m16n8k16.row.col.f32.f16.f16.f32 "
        "{%0,%1,%2,%3},{%4,%5,%6,%7},{%8,%9},{%0,%1,%2,%3};"
        : "+f"(d[0]), "+f"(d[1]), "+f"(d[2]), "+f"(d[3])
        : "r"(a[0]), "r"(a[1]), "r"(a[2]), "r"(a[3]), "r"(b0), "r"(b1));
}

DI void cp16(uint32_t dst, const void* src) {
    asm volatile("cp.async.cg.shared.global [%0], [%1], 16;" :: "r"(dst), "l"(src));
}
#define CP_COMMIT() asm volatile("cp.async.commit_group;" ::: "memory")
#define CP_WAIT2()  asm volatile("cp.async.wait_group 2;"  ::: "memory")

static const int TILE_B = 10240;

// ---------------------------------------------------------------------------
// Unified GEMM, 128x128 tile, 3-stage pipeline, 2 CTAs/SM.
// MODE 0: qp = q@Wq^T + bq       -> g_qh_h        grid(8, 32)  cp.async A, 2-pass
// MODE 1: vp = v@Wv^T + bias+loc -> g_vh_h,g_vhT  grid(8, 512) cp.async A, 1-pass
// MODE 2: score: e=exp(s-m_tile) -> attn + (m,l)  grid(16,256) cp.async A, 1-pass
// MODE 3: out = P@vh, P=e*corr   -> out; attn = P grid(256)    reg A, 1-pass
// ---------------------------------------------------------------------------
template <int MODE>
__global__ void __launch_bounds__(256, 2)
mma_gemm(const float* __restrict__ Ain, const float* __restrict__ biasv,
         const float* __restrict__ la, float* __restrict__ dsto)
{
    extern __shared__ char sm[];
    const uint32_t smb = smem_u32(sm);
    const int t = threadIdx.x, lane = t & 31, w = t >> 5;
    const int wm0 = (w & 3) * 32, wn0 = (w >> 2) * 64;

    constexpr int  K    = (MODE < 2) ? HID : (MODE == 2 ? 128 : VL);
    constexpr int  NC   = K / 32;
    constexpr int  NPA  = (MODE == 0) ? 2 : 1;
    constexpr int  NT   = (MODE == 0) ? 3 : 2;
    constexpr int  BUF  = NT * TILE_B;
    constexpr bool REGA = (MODE == 3);
    constexpr uint32_t BOFF = (uint32_t)(NT - 1) * TILE_B;

    const uint16_t *Ah = nullptr, *Al = nullptr, *Bh = nullptr;
    const float* Afp = nullptr;
    float* attw = nullptr;
    const float* mpRow = nullptr;
    float m_st = 0.f, li_st = 0.f;
    int lda = 0, ldb = 0;
    if (MODE == 0) {
        size_t ao = (size_t)blockIdx.y * 128 * HID, bo = (size_t)blockIdx.x * 128 * HID;
        Ah = s_q_h + ao; Al = s_q_l + ao; Bh = s_Wq_h + bo; lda = ldb = HID;
    } else if (MODE == 1) {
        size_t ao = (size_t)blockIdx.y * 128 * HID, bo = (size_t)blockIdx.x * 128 * HID;
        Ah = s_v_h + ao; Bh = s_Wv_h + bo; lda = ldb = HID;
    } else if (MODE == 2) {
        Ah = g_qh_h + (size_t)blockIdx.y * QL * 128;
        Bh = g_vh_h + (size_t)blockIdx.y * VL * 128 + (size_t)blockIdx.x * 128 * 128;
        lda = ldb = 128;
    } else {
        Afp  = Ain + (size_t)blockIdx.x * QL * VL;
        attw = (float*)Ain + (size_t)blockIdx.x * QL * VL;
        Bh   = g_vhT_h + (size_t)blockIdx.x * 128 * VL; ldb = VL;
        // merge softmax partials for this loader thread's row
        const int myrow = t >> 1;
        mpRow = g_mp + (size_t)blockIdx.x * 2048 + myrow;
        const float* lp = g_lp + (size_t)blockIdx.x * 2048 + myrow;
        float m = -1e30f;
#pragma unroll
        for (int i = 0; i < 16; i++) m = fmaxf(m, mpRow[i * 128]);
        float l = 0.f;
#pragma unroll
        for (int i = 0; i < 16; i++) l += lp[i * 128] * __expf(mpRow[i * 128] - m);
        m_st = m; li_st = 1.0f / l;
    }

    float acc[2][8][4];
#pragma unroll
    for (int i = 0; i < 2; i++)
#pragma unroll
        for (int j = 0; j < 8; j++)
#pragma unroll
            for (int k = 0; k < 4; k++) acc[i][j][k] = 0.f;

    // ---- cp.async loaders ----
    auto cp_chunk = [&](int buf, int c) {   // modes 0/1/2: NT tiles
        uint32_t sb = smb + buf * BUF;
#pragma unroll
        for (int i = 0; i < NT * 2; i++) {
            int idx = t + 256 * i;
            int tile = idx >> 9, r = (idx >> 2) & 127, s = idx & 3;
            const uint16_t* base; int ld; uint32_t doff;
            if (NT == 2) { base = tile ? Bh : Ah; ld = tile ? ldb : lda; doff = tile ? TILE_B : 0u; }
            else {
                base = (tile == 0) ? Ah : (tile == 1) ? Al : Bh;
                ld = (tile == 2) ? ldb : lda;
                doff = (uint32_t)tile * TILE_B;
            }
            cp16(sb + doff + r * 80 + s * 16, base + (size_t)r * ld + c * 32 + s * 8);
        }
    };
    auto cp_chunk_b = [&](int buf, int c) { // MODE 3: B only
        uint32_t sb = smb + buf * BUF + BOFF;
#pragma unroll
        for (int i = 0; i < 2; i++) {
            int idx = t + 256 * i;
            int r = (idx >> 2) & 127, s = idx & 3;
            cp16(sb + r * 80 + s * 16, Bh + (size_t)r * ldb + c * 32 + s * 8);
        }
    };

    auto compute = [&](uint32_t sbuf) {
#pragma unroll
        for (int ks = 0; ks < 2; ks++) {
            const uint32_t rowsel = (uint32_t)(lane & 15) * 80
                                  + (uint32_t)((lane >> 4) + ks * 2) * 16;
            uint32_t aH[2][4], bH[4][4];
#pragma unroll
            for (int mt = 0; mt < 2; mt++)
                ldm4(aH[mt], sbuf + (uint32_t)(wm0 + mt * 16) * 80 + rowsel);
#pragma unroll
            for (int g = 0; g < 4; g++)
                ldm4(bH[g], sbuf + BOFF + (uint32_t)(wn0 + g * 16) * 80 + rowsel);
#pragma unroll
            for (int mt = 0; mt < 2; mt++)
#pragma unroll
                for (int g = 0; g < 4; g++) {
                    mma16816(acc[mt][2 * g],     aH[mt], bH[g][0], bH[g][2]);
                    mma16816(acc[mt][2 * g + 1], aH[mt], bH[g][1], bH[g][3]);
                }
            if (NPA == 2) {
#pragma unroll
                for (int mt = 0; mt < 2; mt++)
                    ldm4(aH[mt], sbuf + TILE_B + (uint32_t)(wm0 + mt * 16) * 80 + rowsel);
#pragma unroll
                for (int mt = 0; mt < 2; mt++)
#pragma unroll
                    for (int g = 0; g < 4; g++) {
                        mma16816(acc[mt][2 * g],     aH[mt], bH[g][0], bH[g][2]);
                        mma16816(acc[mt][2 * g + 1], aH[mt], bH[g][1], bH[g][3]);
                    }
            }
        }
    };

    // ---- MODE 3 register A path: e -> P = e*corr, write attn, fp16 to smem ----
    float4 arg[4];
    const float* apA = REGA ? Afp + (size_t)(t >> 1) * VL + (t & 1) * 16 : nullptr;
    float* awA = REGA ? attw + (size_t)(t >> 1) * VL + (t & 1) * 16 : nullptr;
    const uint32_t aoff = (t >> 1) * 80 + (t & 1) * 32;

    auto LD_A = [&](int c) {
#pragma unroll
        for (int j = 0; j < 4; j++) arg[j] = *(const float4*)(apA + (size_t)c * 32 + j * 4);
    };
    auto STS_A = [&](int buf, int ch) {
        char* bb = sm + buf * BUF;
        float cr = __expf(mpRow[(ch >> 2) * 128] - m_st) * li_st;
        float* aw = awA + (size_t)ch * 32;
        float4 P[4];
#pragma unroll
        for (int j = 0; j < 4; j++) {
            P[j].x = arg[j].x * cr; P[j].y = arg[j].y * cr;
            P[j].z = arg[j].z * cr; P[j].w = arg[j].w * cr;
            *(float4*)(aw + j * 4) = P[j];
        }
        uint4 H;
        H.x = pk2h(P[0].x, P[0].y); H.y = pk2h(P[0].z, P[0].w);
        H.z = pk2h(P[1].x, P[1].y); H.w = pk2h(P[1].z, P[1].w);
        *(uint4*)(bb + aoff) = H;
        H.x = pk2h(P[2].x, P[2].y); H.y = pk2h(P[2].z, P[2].w);
        H.z = pk2h(P[3].x, P[3].y); H.w = pk2h(P[3].z, P[3].w);
        *(uint4*)(bb + aoff + 16) = H;
    };

    // ---- prologue ----
    if (REGA) {
        LD_A(0); STS_A(0, 0);
        LD_A(1); STS_A(1, 1);
        LD_A(2); STS_A(2, 2);
        LD_A(3);
        cp_chunk_b(0, 0); CP_COMMIT();
        cp_chunk_b(1, 1); CP_COMMIT();
        cp_chunk_b(2, 2); CP_COMMIT();
    } else {
        cp_chunk(0, 0); CP_COMMIT();
        cp_chunk(1, 1); CP_COMMIT();
        cp_chunk(2, 2); CP_COMMIT();
    }

    int buf = 0;
    for (int c = 0; c < NC; c++) {
        CP_WAIT2();
        __syncthreads();
        compute(smb + buf * BUF);
        __syncthreads();
        if (c + 3 < NC) {
            if (REGA) { STS_A(buf, c + 3); cp_chunk_b(buf, c + 3); }
            else      cp_chunk(buf, c + 3);
        }
        CP_COMMIT();
        if (REGA && c + 4 < NC) LD_A(c + 4);
        buf = (buf == 2) ? 0 : buf + 1;
    }

    // ------------------------- epilogues -------------------------
    if (MODE == 2) {
        // attn <- e = exp(s*sc - m_tile); partials (m_tile, l_tile) -> g_mp/g_lp
        float* pm = (float*)(sm + 34048);   // [2][128]
        float* mM = pm + 256;               // [128]
        float* pl = mM + 128;               // [2][128]
        const float sc = 0.08838834764831845f;
#pragma unroll
        for (int mt = 0; mt < 2; mt++)
#pragma unroll
            for (int h2 = 0; h2 < 2; h2++) {
                const int row = wm0 + mt * 16 + (lane >> 2) + h2 * 8;
                float mx = -1e30f;
#pragma unroll
                for (int nt = 0; nt < 8; nt++)
                    mx = fmaxf(mx, fmaxf(acc[mt][nt][2 * h2], acc[mt][nt][2 * h2 + 1]));
                mx *= sc;
                mx = fmaxf(mx, __shfl_xor_sync(~0u, mx, 1));
                mx = fmaxf(mx, __shfl_xor_sync(~0u, mx, 2));
                if ((lane & 3) == 0) pm[(w >> 2) * 128 + row] = mx;
            }
        __syncthreads();
        if (t < 128) mM[t] = fmaxf(pm[t], pm[128 + t]);
        __syncthreads();
#pragma unroll
        for (int mt = 0; mt < 2; mt++)
#pragma unroll
            for (int h2 = 0; h2 < 2; h2++) {
                const int row = wm0 + mt * 16 + (lane >> 2) + h2 * 8;
                const float mm = mM[row];
                float* ad = dsto + ((size_t)blockIdx.y * QL + row) * VL + blockIdx.x * 128;
                float l = 0.f;
#pragma unroll
                for (int nt = 0; nt < 8; nt++) {
                    const int col = wn0 + nt * 8 + 2 * (lane & 3);
                    float e0 = __expf(acc[mt][nt][2 * h2]     * sc - mm);
                    float e1 = __expf(acc[mt][nt][2 * h2 + 1] * sc - mm);
                    *(float2*)(ad + col) = make_float2(e0, e1);
                    l += e0 + e1;
                }
                l += __shfl_xor_sync(~0u, l, 1);
                l += __shfl_xor_sync(~0u, l, 2);
                if ((lane & 3) == 0) pl[(w >> 2) * 128 + row] = l;
            }
        __syncthreads();
        if (t < 128) {
            size_t o = ((size_t)blockIdx.y * 16 + blockIdx.x) * 128 + t;
            g_mp[o] = mM[t];
            g_lp[o] = pl[t] + pl[128 + t];
        }
        return;
    }

    float* vec = (float*)(sm + 34048);
    if (MODE == 0) {
        if (t < 128) vec[t] = biasv[blockIdx.x * 128 + t];
    }
    if (MODE == 1) {
        if (t < 128) {
            vec[t]       = biasv[blockIdx.x * 128 + t] + g_Cc[t];
            vec[128 + t] = g_A0[t];
            vec[256 + t] = g_A1[t];
            vec[384 + t] = g_A2[t];
        }
        const int b = blockIdx.y >> 4, h = blockIdx.x;
        const int vpos0 = (blockIdx.y & 15) * 128;
        const float* lar = la + (size_t)(b * 8 + h) * VL;
        if (t < 130) {
            int g = vpos0 - 1 + t;
            vec[512 + t] = (g >= 0 && g < VL) ? lar[g] : 0.f;
        }
    }
    __syncthreads();

#pragma unroll
    for (int mt = 0; mt < 2; mt++) {
#pragma unroll
        for (int h2 = 0; h2 < 2; h2++) {
            const int row = wm0 + mt * 16 + (lane >> 2) + h2 * 8;
            size_t obase = 0;
            float* dst = nullptr;
            float lm1 = 0.f, l0 = 0.f, lp1 = 0.f;
            if (MODE == 0) {
                obase = (((size_t)(blockIdx.x * 32 + blockIdx.y)) * QL + row) * 128;
            } else if (MODE == 1) {
                int b = blockIdx.y >> 4, h = blockIdx.x;
                int vpos0 = (blockIdx.y & 15) * 128;
                lm1 = vec[512 + row]; l0 = vec[513 + row]; lp1 = vec[514 + row];
                obase = (((size_t)(h * 32 + b)) * VL + vpos0 + row) * 128;
            } else {
                int h = blockIdx.x >> 5, b = blockIdx.x & 31;
                dst = dsto + ((size_t)(b * QL + row)) * HID + h * 128;
            }
#pragma unroll
            for (int nt = 0; nt < 8; nt++) {
                const int col = wn0 + nt * 8 + 2 * (lane & 3);
                float x = acc[mt][nt][2 * h2];
                float y = acc[mt][nt][2 * h2 + 1];
                if (MODE == 0) {
                    x += vec[col]; y += vec[col + 1];
                    *(uint32_t*)&g_qh_h[obase + col] = pk2h(x, y);
                } else if (MODE == 1) {
                    x += vec[col]     + vec[128 + col]     * lm1 + vec[256 + col]     * l0 + vec[384 + col]     * lp1;
                    y += vec[col + 1] + vec[128 + col + 1] * lm1 + vec[256 + col + 1] * l0 + vec[384 + col + 1] * lp1;
                    uint32_t hi = pk2h(x, y);
                    *(uint32_t*)&g_vh_h[obase + col] = hi;
                    *(uint32_t*)(sm + (row * 65 + (col >> 1)) * 4) = hi;
                } else {
                    *(float2*)(dst + col) = make_float2(x, y);
                }
            }
        }
    }

    if (MODE == 1) {
        __syncthreads();
        const int b = blockIdx.y >> 4, h = blockIdx.x;
        const int vpos0 = (blockIdx.y & 15) * 128;
        const int d = t >> 1, vh2 = t & 1;
        size_t ob = (((size_t)(h * 32 + b)) * 128 + d) * VL + vpos0 + vh2 * 64;
#pragma unroll
        for (int blk = 0; blk < 8; blk++) {
            uint16_t e[8];
#pragma unroll
            for (int j = 0; j < 8; j++) {
                int v = vh2 * 64 + blk * 8 + j;
                e[j] = *(uint16_t*)(sm + (v * 65 + (d >> 1)) * 4 + (d & 1) * 2);
            }
            uint4 o;
            o.x = (uint32_t)e[0] | ((uint32_t)e[1] << 16);
            o.y = (uint32_t)e[2] | ((uint32_t)e[3] << 16);
            o.z = (uint32_t)e[4] | ((uint32_t)e[5] << 16);
            o.w = (uint32_t)e[6] | ((uint32_t)e[7] << 16);
            *(uint4*)&g_vhT_h[ob + blk * 8] = o;
        }
    }
}

// ---------------------------------------------------------------------------
// fp32 -> fp16 splits
// ---------------------------------------------------------------------------
DI void split2_body(const float4* __restrict__ in, uint16_t* oh, uint16_t* ol, int n4) {
    int i = blockIdx.x * 256 + threadIdx.x;
    if (i >= n4) return;
    float4 x = in[i];
    uint32_t l0, l1;
    uint32_t h0 = sp2h(x.x, x.y, l0), h1 = sp2h(x.z, x.w, l1);
    uint2 H; H.x = h0; H.y = h1;
    *(uint2*)&oh[(size_t)i * 4] = H;
    uint2 L; L.x = l0; L.y = l1;
    *(uint2*)&ol[(size_t)i * 4] = L;
}
DI void split1_body(const float4* __restrict__ in, uint16_t* oh, int n4) {
    int i = blockIdx.x * 256 + threadIdx.x;
    if (i >= n4) return;
    float4 x = in[i];
    uint2 H;
    H.x = pk2h(x.x, x.y); H.y = pk2h(x.z, x.w);
    *(uint2*)&oh[(size_t)i * 4] = H;
}
__global__ void split_q_k(const float4* in)  { split2_body(in, s_q_h, s_q_l, 1048576); }
__global__ void split_v_k(const float4* in)  { split1_body(in, s_v_h, 16777216); }
__global__ void split_wq_k(const float4* in) { split1_body(in, s_Wq_h, 262144); }
__global__ void split_wv_k(const float4* in) { split1_body(in, s_Wv_h, 262144); }

// ---------------------------------------------------------------------------
__global__ void prep_kernel(const float* __restrict__ conv_w,
                            const float* __restrict__ conv_b,
                            const float* __restrict__ Wloc)
{
    int d = threadIdx.x;
    float a0 = 0.f, a1 = 0.f, a2 = 0.f, c = 0.f;
#pragma unroll
    for (int cc = 0; cc < 10; cc++) {
        float wl = Wloc[d * 10 + cc];
        a0 += wl * conv_w[cc * 3 + 0];
        a1 += wl * conv_w[cc * 3 + 1];
        a2 += wl * conv_w[cc * 3 + 2];
        c  += wl * conv_b[cc];
    }
    g_A0[d] = a0; g_A1[d] = a1; g_A2[d] = a2; g_Cc[d] = c;
}

// ---------------------------------------------------------------------------
extern "C" void kernel_launch(void* const* d_in, const int* in_sizes, int n_in,
                              void* d_out, int out_size)
{
    const float* q         = (const float*)d_in[0];
    const float* v         = (const float*)d_in[1];
    const float* last_attn = (const float*)d_in[2];
    const float* conv_w    = (const float*)d_in[3];
    const float* conv_b    = (const float*)d_in[4];
    const float* Wq        = (const float*)d_in[5];
    const float* bq        = (const float*)d_in[6];
    const float* Wv        = (const float*)d_in[7];
    const float* Wloc      = (const float*)d_in[8];
    const float* bias      = (const float*)d_in[9];

    float* out  = (float*)d_out;
    float* attn = out + 4194304;

    const int SM3 = 3 * 3 * TILE_B;   // 92160 (mode 0)
    const int SM2 = 3 * 2 * TILE_B;   // 61440 (modes 1/2/3)

    static bool attr_done = false;
    if (!attr_done) {
        cudaFuncSetAttribute(mma_gemm<0>, cudaFuncAttributeMaxDynamicSharedMemorySize, SM3);
        cudaFuncSetAttribute(mma_gemm<1>, cudaFuncAttributeMaxDynamicSharedMemorySize, SM2);
        cudaFuncSetAttribute(mma_gemm<2>, cudaFuncAttributeMaxDynamicSharedMemorySize, SM2);
        cudaFuncSetAttribute(mma_gemm<3>, cudaFuncAttributeMaxDynamicSharedMemorySize, SM2);
        attr_done = true;
    }

    prep_kernel<<<1, 128>>>(conv_w, conv_b, Wloc);
    split_q_k <<<4096,  256>>>((const float4*)q);
    split_v_k <<<65536, 256>>>((const float4*)v);
    split_wq_k<<<1024,  256>>>((const float4*)Wq);
    split_wv_k<<<1024,  256>>>((const float4*)Wv);

    mma_gemm<0><<<dim3(8, 32),   256, SM3>>>(nullptr, bq,   nullptr,   nullptr);
    mma_gemm<1><<<dim3(8, 512),  256, SM2>>>(nullptr, bias, last_attn, nullptr);
    mma_gemm<2><<<dim3(16, 256), 256, SM2>>>(nullptr, nullptr, nullptr, attn);
    mma_gemm<3><<<256, 256, SM2>>>(attn, nullptr, nullptr, out);
}

// round 12
// speedup vs baseline: 1.1947x; 1.0774x over previous
#include <cuda_runtime.h>
#include <cuda_fp16.h>
#include <cstdint>

#define DI __device__ __forceinline__

static const int QL  = 128;
static const int VL  = 2048;
static const int HID = 1024;

// ---------------------------------------------------------------------------
// Scratch (device globals; no runtime allocation allowed). fp16 operands.
// ---------------------------------------------------------------------------
__device__ uint16_t s_q_h[4194304], s_q_l[4194304];     // split q (2-pass A)
__device__ uint16_t s_v_h[67108864];                    // v hi (1-pass A)
__device__ uint16_t s_Wq_h[1048576];                    // Wq hi
__device__ uint16_t s_Wv_h[1048576];                    // Wv hi
__device__ uint16_t g_qh_h[4194304];                    // qp result [n][q][d]
__device__ uint16_t g_vh_h[67108864];                   // vp result [n][v][d]
__device__ float g_A0[128], g_A1[128], g_A2[128], g_Cc[128];
__device__ float g_mp[524288], g_lp[524288];            // softmax partials [n][16][128]

// ---------------------------------------------------------------------------
DI uint32_t smem_u32(const void* p) {
    uint32_t a;
    asm("{ .reg .u64 t; cvta.to.shared.u64 t, %1; cvt.u32.u64 %0, t; }" : "=r"(a) : "l"(p));
    return a;
}

DI uint32_t sp2h(float a, float b, uint32_t& lo) {
    __half2 h = __floats2half2_rn(a, b);
    float2 f = __half22float2(h);
    __half2 l = __floats2half2_rn(a - f.x, b - f.y);
    lo = *(uint32_t*)&l;
    return *(uint32_t*)&h;
}
DI uint32_t pk2h(float a, float b) {
    __half2 h = __floats2half2_rn(a, b);
    return *(uint32_t*)&h;
}

DI void ldm4(uint32_t* r, uint32_t a) {
    asm volatile("ldmatrix.sync.aligned.m8n8.x4.shared.b16 {%0,%1,%2,%3}, [%4];"
        : "=r"(r[0]), "=r"(r[1]), "=r"(r[2]), "=r"(r[3]) : "r"(a));
}
DI void ldm4t(uint32_t* r, uint32_t a) {
    asm volatile("ldmatrix.sync.aligned.m8n8.x4.trans.shared.b16 {%0,%1,%2,%3}, [%4];"
        : "=r"(r[0]), "=r"(r[1]), "=r"(r[2]), "=r"(r[3]) : "r"(a));
}

DI void mma16816(float* d, const uint32_t* a, uint32_t b0, uint32_t b1) {
    asm volatile("mma.sync.aligned.m16n8k16.row.col.f32.f16.f16.f32 "
        "{%0,%1,%2,%3},{%4,%5,%6,%7},{%8,%9},{%0,%1,%2,%3};"
        : "+f"(d[0]), "+f"(d[1]), "+f"(d[2]), "+f"(d[3])
        : "r"(a[0]), "r"(a[1]), "r"(a[2]), "r"(a[3]), "r"(b0), "r"(b1));
}

DI void cp16(uint32_t dst, const void* src) {
    asm volatile("cp.async.cg.shared.global [%0], [%1], 16;" :: "r"(dst), "l"(src));
}
#define CP_COMMIT() asm volatile("cp.async.commit_group;" ::: "memory")
#define CP_WAIT2()  asm volatile("cp.async.wait_group 2;"  ::: "memory")

static const int TILE_B = 10240;
static const int BT3    = 8704;          // MODE 3 B tile: 32 rows x 272B

// ---------------------------------------------------------------------------
// Unified GEMM, 128x128 tile, 3-stage pipeline, 2 CTAs/SM.
// MODE 0: qp = q@Wq^T + bq       -> g_qh_h       grid(8, 32)  cp.async A, 2-pass
// MODE 1: vp = v@Wv^T + bias+loc -> g_vh_h       grid(8, 512) cp.async A, 1-pass
// MODE 2: score: e=exp(s-m_tile) -> attn + (m,l) grid(16,256) cp.async A, 1-pass
// MODE 3: out = P@vh, P=e*corr   -> out; attn=P  grid(256)    reg A; B via ldmatrix.trans
// ---------------------------------------------------------------------------
template <int MODE>
__global__ void __launch_bounds__(256, 2)
mma_gemm(const float* __restrict__ Ain, const float* __restrict__ biasv,
         const float* __restrict__ la, float* __restrict__ dsto)
{
    extern __shared__ char sm[];
    const uint32_t smb = smem_u32(sm);
    const int t = threadIdx.x, lane = t & 31, w = t >> 5;
    const int wm0 = (w & 3) * 32, wn0 = (w >> 2) * 64;

    constexpr int  K    = (MODE < 2) ? HID : (MODE == 2 ? 128 : VL);
    constexpr int  NC   = K / 32;
    constexpr int  NPA  = (MODE == 0) ? 2 : 1;
    constexpr int  NT   = (MODE == 0) ? 3 : 2;
    constexpr int  BUF  = (MODE == 3) ? (TILE_B + BT3) : NT * TILE_B;
    constexpr bool REGA = (MODE == 3);
    constexpr uint32_t BOFF = (MODE == 3) ? (uint32_t)TILE_B
                                          : (uint32_t)(NT - 1) * TILE_B;

    const uint16_t *Ah = nullptr, *Al = nullptr, *Bh = nullptr;
    const float* Afp = nullptr;
    float* attw = nullptr;
    const float* mpRow = nullptr;
    float m_st = 0.f, li_st = 0.f;
    int lda = 0, ldb = 0;
    if (MODE == 0) {
        size_t ao = (size_t)blockIdx.y * 128 * HID, bo = (size_t)blockIdx.x * 128 * HID;
        Ah = s_q_h + ao; Al = s_q_l + ao; Bh = s_Wq_h + bo; lda = ldb = HID;
    } else if (MODE == 1) {
        size_t ao = (size_t)blockIdx.y * 128 * HID, bo = (size_t)blockIdx.x * 128 * HID;
        Ah = s_v_h + ao; Bh = s_Wv_h + bo; lda = ldb = HID;
    } else if (MODE == 2) {
        Ah = g_qh_h + (size_t)blockIdx.y * QL * 128;
        Bh = g_vh_h + (size_t)blockIdx.y * VL * 128 + (size_t)blockIdx.x * 128 * 128;
        lda = ldb = 128;
    } else {
        Afp  = Ain + (size_t)blockIdx.x * QL * VL;
        attw = (float*)Ain + (size_t)blockIdx.x * QL * VL;
        Bh   = g_vh_h + (size_t)blockIdx.x * VL * 128; ldb = 128;
        // merge softmax partials for this loader thread's row
        const int myrow = t >> 1;
        mpRow = g_mp + (size_t)blockIdx.x * 2048 + myrow;
        const float* lp = g_lp + (size_t)blockIdx.x * 2048 + myrow;
        float m = -1e30f;
#pragma unroll
        for (int i = 0; i < 16; i++) m = fmaxf(m, mpRow[i * 128]);
        float l = 0.f;
#pragma unroll
        for (int i = 0; i < 16; i++) l += lp[i * 128] * __expf(mpRow[i * 128] - m);
        m_st = m; li_st = 1.0f / l;
    }

    float acc[2][8][4];
#pragma unroll
    for (int i = 0; i < 2; i++)
#pragma unroll
        for (int j = 0; j < 8; j++)
#pragma unroll
            for (int k = 0; k < 4; k++) acc[i][j][k] = 0.f;

    // ---- cp.async loaders ----
    auto cp_chunk = [&](int buf, int c) {   // modes 0/1/2: NT tiles, 80B pitch
        uint32_t sb = smb + buf * BUF;
#pragma unroll
        for (int i = 0; i < NT * 2; i++) {
            int idx = t + 256 * i;
            int tile = idx >> 9, r = (idx >> 2) & 127, s = idx & 3;
            const uint16_t* base; int ld; uint32_t doff;
            if (NT == 2) { base = tile ? Bh : Ah; ld = tile ? ldb : lda; doff = tile ? TILE_B : 0u; }
            else {
                base = (tile == 0) ? Ah : (tile == 1) ? Al : Bh;
                ld = (tile == 2) ? ldb : lda;
                doff = (uint32_t)tile * TILE_B;
            }
            cp16(sb + doff + r * 80 + s * 16, base + (size_t)r * ld + c * 32 + s * 8);
        }
    };
    auto cp_chunk_b3 = [&](int buf, int c) { // MODE 3: B = vh rows [c*32,+32) x 128d, 272B pitch
        uint32_t sb = smb + buf * BUF + BOFF;
#pragma unroll
        for (int i = 0; i < 2; i++) {
            int idx = t + 256 * i;
            int r = idx >> 4, s = idx & 15;
            cp16(sb + r * 272 + s * 16, Bh + (size_t)(c * 32 + r) * 128 + s * 8);
        }
    };

    auto compute = [&](uint32_t sbuf) {
#pragma unroll
        for (int ks = 0; ks < 2; ks++) {
            const uint32_t rowsel = (uint32_t)(lane & 15) * 80
                                  + (uint32_t)((lane >> 4) + ks * 2) * 16;
            uint32_t aH[2][4], bH[4][4];
#pragma unroll
            for (int mt = 0; mt < 2; mt++)
                ldm4(aH[mt], sbuf + (uint32_t)(wm0 + mt * 16) * 80 + rowsel);
            if (MODE == 3) {
                // trans B: [K=v][N=d]; matrices (k0-7,nlo)(k0-7,nhi)(k8-15,nlo)(k8-15,nhi)
                const uint32_t rsel = (uint32_t)((lane & 7) + ((lane >> 4) << 3) + ks * 16) * 272
                                    + (uint32_t)(((lane >> 3) & 1) << 4);
#pragma unroll
                for (int g = 0; g < 4; g++)
                    ldm4t(bH[g], sbuf + BOFF + rsel + (uint32_t)(wn0 + g * 16) * 2);
            } else {
#pragma unroll
                for (int g = 0; g < 4; g++)
                    ldm4(bH[g], sbuf + BOFF + (uint32_t)(wn0 + g * 16) * 80 + rowsel);
            }
#pragma unroll
            for (int mt = 0; mt < 2; mt++)
#pragma unroll
                for (int g = 0; g < 4; g++) {
                    mma16816(acc[mt][2 * g],     aH[mt], bH[g][0], bH[g][2]);
                    mma16816(acc[mt][2 * g + 1], aH[mt], bH[g][1], bH[g][3]);
                }
            if (NPA == 2) {
#pragma unroll
                for (int mt = 0; mt < 2; mt++)
                    ldm4(aH[mt], sbuf + TILE_B + (uint32_t)(wm0 + mt * 16) * 80 + rowsel);
#pragma unroll
                for (int mt = 0; mt < 2; mt++)
#pragma unroll
                    for (int g = 0; g < 4; g++) {
                        mma16816(acc[mt][2 * g],     aH[mt], bH[g][0], bH[g][2]);
                        mma16816(acc[mt][2 * g + 1], aH[mt], bH[g][1], bH[g][3]);
                    }
            }
        }
    };

    // ---- MODE 3 register A path: e -> P = e*corr, write attn, fp16 to smem ----
    float4 arg[4];
    const float* apA = REGA ? Afp + (size_t)(t >> 1) * VL + (t & 1) * 16 : nullptr;
    float* awA = REGA ? attw + (size_t)(t >> 1) * VL + (t & 1) * 16 : nullptr;
    const uint32_t aoff = (t >> 1) * 80 + (t & 1) * 32;

    auto LD_A = [&](int c) {
#pragma unroll
        for (int j = 0; j < 4; j++) arg[j] = *(const float4*)(apA + (size_t)c * 32 + j * 4);
    };
    auto STS_A = [&](int buf, int ch) {
        char* bb = sm + buf * BUF;
        float cr = __expf(mpRow[(ch >> 2) * 128] - m_st) * li_st;
        float* aw = awA + (size_t)ch * 32;
        float4 P[4];
#pragma unroll
        for (int j = 0; j < 4; j++) {
            P[j].x = arg[j].x * cr; P[j].y = arg[j].y * cr;
            P[j].z = arg[j].z * cr; P[j].w = arg[j].w * cr;
            *(float4*)(aw + j * 4) = P[j];
        }
        uint4 H;
        H.x = pk2h(P[0].x, P[0].y); H.y = pk2h(P[0].z, P[0].w);
        H.z = pk2h(P[1].x, P[1].y); H.w = pk2h(P[1].z, P[1].w);
        *(uint4*)(bb + aoff) = H;
        H.x = pk2h(P[2].x, P[2].y); H.y = pk2h(P[2].z, P[2].w);
        H.z = pk2h(P[3].x, P[3].y); H.w = pk2h(P[3].z, P[3].w);
        *(uint4*)(bb + aoff + 16) = H;
    };

    // ---- prologue ----
    if (REGA) {
        LD_A(0); STS_A(0, 0);
        LD_A(1); STS_A(1, 1);
        LD_A(2); STS_A(2, 2);
        LD_A(3);
        cp_chunk_b3(0, 0); CP_COMMIT();
        cp_chunk_b3(1, 1); CP_COMMIT();
        cp_chunk_b3(2, 2); CP_COMMIT();
    } else {
        cp_chunk(0, 0); CP_COMMIT();
        cp_chunk(1, 1); CP_COMMIT();
        cp_chunk(2, 2); CP_COMMIT();
    }

    int buf = 0;
    for (int c = 0; c < NC; c++) {
        CP_WAIT2();
        __syncthreads();
        compute(smb + buf * BUF);
        __syncthreads();
        if (c + 3 < NC) {
            if (REGA) { STS_A(buf, c + 3); cp_chunk_b3(buf, c + 3); }
            else      cp_chunk(buf, c + 3);
        }
        CP_COMMIT();
        if (REGA && c + 4 < NC) LD_A(c + 4);
        buf = (buf == 2) ? 0 : buf + 1;
    }

    // ------------------------- epilogues -------------------------
    if (MODE == 2) {
        // attn <- e = exp(s*sc - m_tile); partials (m_tile, l_tile) -> g_mp/g_lp
        float* pm = (float*)(sm + 34048);   // [2][128]
        float* mM = pm + 256;               // [128]
        float* pl = mM + 128;               // [2][128]
        const float sc = 0.08838834764831845f;
#pragma unroll
        for (int mt = 0; mt < 2; mt++)
#pragma unroll
            for (int h2 = 0; h2 < 2; h2++) {
                const int row = wm0 + mt * 16 + (lane >> 2) + h2 * 8;
                float mx = -1e30f;
#pragma unroll
                for (int nt = 0; nt < 8; nt++)
                    mx = fmaxf(mx, fmaxf(acc[mt][nt][2 * h2], acc[mt][nt][2 * h2 + 1]));
                mx *= sc;
                mx = fmaxf(mx, __shfl_xor_sync(~0u, mx, 1));
                mx = fmaxf(mx, __shfl_xor_sync(~0u, mx, 2));
                if ((lane & 3) == 0) pm[(w >> 2) * 128 + row] = mx;
            }
        __syncthreads();
        if (t < 128) mM[t] = fmaxf(pm[t], pm[128 + t]);
        __syncthreads();
#pragma unroll
        for (int mt = 0; mt < 2; mt++)
#pragma unroll
            for (int h2 = 0; h2 < 2; h2++) {
                const int row = wm0 + mt * 16 + (lane >> 2) + h2 * 8;
                const float mm = mM[row];
                float* ad = dsto + ((size_t)blockIdx.y * QL + row) * VL + blockIdx.x * 128;
                float l = 0.f;
#pragma unroll
                for (int nt = 0; nt < 8; nt++) {
                    const int col = wn0 + nt * 8 + 2 * (lane & 3);
                    float e0 = __expf(acc[mt][nt][2 * h2]     * sc - mm);
                    float e1 = __expf(acc[mt][nt][2 * h2 + 1] * sc - mm);
                    *(float2*)(ad + col) = make_float2(e0, e1);
                    l += e0 + e1;
                }
                l += __shfl_xor_sync(~0u, l, 1);
                l += __shfl_xor_sync(~0u, l, 2);
                if ((lane & 3) == 0) pl[(w >> 2) * 128 + row] = l;
            }
        __syncthreads();
        if (t < 128) {
            size_t o = ((size_t)blockIdx.y * 16 + blockIdx.x) * 128 + t;
            g_mp[o] = mM[t];
            g_lp[o] = pl[t] + pl[128 + t];
        }
        return;
    }

    float* vec = (float*)(sm + 34048);
    if (MODE == 0) {
        if (t < 128) vec[t] = biasv[blockIdx.x * 128 + t];
    }
    if (MODE == 1) {
        if (t < 128) {
            vec[t]       = biasv[blockIdx.x * 128 + t] + g_Cc[t];
            vec[128 + t] = g_A0[t];
            vec[256 + t] = g_A1[t];
            vec[384 + t] = g_A2[t];
        }
        const int b = blockIdx.y >> 4, h = blockIdx.x;
        const int vpos0 = (blockIdx.y & 15) * 128;
        const float* lar = la + (size_t)(b * 8 + h) * VL;
        if (t < 130) {
            int g = vpos0 - 1 + t;
            vec[512 + t] = (g >= 0 && g < VL) ? lar[g] : 0.f;
        }
    }
    __syncthreads();

#pragma unroll
    for (int mt = 0; mt < 2; mt++) {
#pragma unroll
        for (int h2 = 0; h2 < 2; h2++) {
            const int row = wm0 + mt * 16 + (lane >> 2) + h2 * 8;
            size_t obase = 0;
            float* dst = nullptr;
            float lm1 = 0.f, l0 = 0.f, lp1 = 0.f;
            if (MODE == 0) {
                obase = (((size_t)(blockIdx.x * 32 + blockIdx.y)) * QL + row) * 128;
            } else if (MODE == 1) {
                int b = blockIdx.y >> 4, h = blockIdx.x;
                int vpos0 = (blockIdx.y & 15) * 128;
                lm1 = vec[512 + row]; l0 = vec[513 + row]; lp1 = vec[514 + row];
                obase = (((size_t)(h * 32 + b)) * VL + vpos0 + row) * 128;
            } else {
                int h = blockIdx.x >> 5, b = blockIdx.x & 31;
                dst = dsto + ((size_t)(b * QL + row)) * HID + h * 128;
            }
#pragma unroll
            for (int nt = 0; nt < 8; nt++) {
                const int col = wn0 + nt * 8 + 2 * (lane & 3);
                float x = acc[mt][nt][2 * h2];
                float y = acc[mt][nt][2 * h2 + 1];
                if (MODE == 0) {
                    x += vec[col]; y += vec[col + 1];
                    *(uint32_t*)&g_qh_h[obase + col] = pk2h(x, y);
                } else if (MODE == 1) {
                    x += vec[col]     + vec[128 + col]     * lm1 + vec[256 + col]     * l0 + vec[384 + col]     * lp1;
                    y += vec[col + 1] + vec[128 + col + 1] * lm1 + vec[256 + col + 1] * l0 + vec[384 + col + 1] * lp1;
                    *(uint32_t*)&g_vh_h[obase + col] = pk2h(x, y);
                } else {
                    *(float2*)(dst + col) = make_float2(x, y);
                }
            }
        }
    }
}

// ---------------------------------------------------------------------------
// fp32 -> fp16 splits
// ---------------------------------------------------------------------------
DI void split2_body(const float4* __restrict__ in, uint16_t* oh, uint16_t* ol, int n4) {
    int i = blockIdx.x * 256 + threadIdx.x;
    if (i >= n4) return;
    float4 x = in[i];
    uint32_t l0, l1;
    uint32_t h0 = sp2h(x.x, x.y, l0), h1 = sp2h(x.z, x.w, l1);
    uint2 H; H.x = h0; H.y = h1;
    *(uint2*)&oh[(size_t)i * 4] = H;
    uint2 L; L.x = l0; L.y = l1;
    *(uint2*)&ol[(size_t)i * 4] = L;
}
DI void split1_body(const float4* __restrict__ in, uint16_t* oh, int n4) {
    int i = blockIdx.x * 256 + threadIdx.x;
    if (i >= n4) return;
    float4 x = in[i];
    uint2 H;
    H.x = pk2h(x.x, x.y); H.y = pk2h(x.z, x.w);
    *(uint2*)&oh[(size_t)i * 4] = H;
}
__global__ void split_q_k(const float4* in)  { split2_body(in, s_q_h, s_q_l, 1048576); }
__global__ void split_v_k(const float4* in)  { split1_body(in, s_v_h, 16777216); }
__global__ void split_wq_k(const float4* in) { split1_body(in, s_Wq_h, 262144); }
__global__ void split_wv_k(const float4* in) { split1_body(in, s_Wv_h, 262144); }

// ---------------------------------------------------------------------------
__global__ void prep_kernel(const float* __restrict__ conv_w,
                            const float* __restrict__ conv_b,
                            const float* __restrict__ Wloc)
{
    int d = threadIdx.x;
    float a0 = 0.f, a1 = 0.f, a2 = 0.f, c = 0.f;
#pragma unroll
    for (int cc = 0; cc < 10; cc++) {
        float wl = Wloc[d * 10 + cc];
        a0 += wl * conv_w[cc * 3 + 0];
        a1 += wl * conv_w[cc * 3 + 1];
        a2 += wl * conv_w[cc * 3 + 2];
        c  += wl * conv_b[cc];
    }
    g_A0[d] = a0; g_A1[d] = a1; g_A2[d] = a2; g_Cc[d] = c;
}

// ---------------------------------------------------------------------------
extern "C" void kernel_launch(void* const* d_in, const int* in_sizes, int n_in,
                              void* d_out, int out_size)
{
    const float* q         = (const float*)d_in[0];
    const float* v         = (const float*)d_in[1];
    const float* last_attn = (const float*)d_in[2];
    const float* conv_w    = (const float*)d_in[3];
    const float* conv_b    = (const float*)d_in[4];
    const float* Wq        = (const float*)d_in[5];
    const float* bq        = (const float*)d_in[6];
    const float* Wv        = (const float*)d_in[7];
    const float* Wloc      = (const float*)d_in[8];
    const float* bias      = (const float*)d_in[9];

    float* out  = (float*)d_out;
    float* attn = out + 4194304;

    const int SM3  = 3 * 3 * TILE_B;          // 92160 (mode 0)
    const int SM2  = 3 * 2 * TILE_B;          // 61440 (modes 1/2)
    const int SMO  = 3 * (TILE_B + BT3);      // 56832 (mode 3)

    static cudaStream_t s2 = nullptr;
    static cudaEvent_t evR = nullptr, evJ = nullptr;
    if (!s2) {
        cudaFuncSetAttribute(mma_gemm<0>, cudaFuncAttributeMaxDynamicSharedMemorySize, SM3);
        cudaFuncSetAttribute(mma_gemm<1>, cudaFuncAttributeMaxDynamicSharedMemorySize, SM2);
        cudaFuncSetAttribute(mma_gemm<2>, cudaFuncAttributeMaxDynamicSharedMemorySize, SM2);
        cudaFuncSetAttribute(mma_gemm<3>, cudaFuncAttributeMaxDynamicSharedMemorySize, SMO);
        cudaStreamCreateWithFlags(&s2, cudaStreamNonBlocking);
        cudaEventCreateWithFlags(&evR, cudaEventDisableTiming);
        cudaEventCreateWithFlags(&evJ, cudaEventDisableTiming);
    }

    // fork: qp chain on s2, vp chain on default stream
    cudaEventRecord(evR, 0);
    cudaStreamWaitEvent(s2, evR, 0);

    split_q_k <<<4096, 256, 0, s2>>>((const float4*)q);
    split_wq_k<<<1024, 256, 0, s2>>>((const float4*)Wq);
    mma_gemm<0><<<dim3(8, 32), 256, SM3, s2>>>(nullptr, bq, nullptr, nullptr);
    cudaEventRecord(evJ, s2);

    prep_kernel<<<1, 128>>>(conv_w, conv_b, Wloc);
    split_v_k <<<65536, 256>>>((const float4*)v);
    split_wv_k<<<1024,  256>>>((const float4*)Wv);
    mma_gemm<1><<<dim3(8, 512), 256, SM2>>>(nullptr, bias, last_attn, nullptr);

    // join: score needs qp (s2) and vp (default)
    cudaStreamWaitEvent(0, evJ, 0);
    mma_gemm<2><<<dim3(16, 256), 256, SM2>>>(nullptr, nullptr, nullptr, attn);
    mma_gemm<3><<<256, 256, SMO>>>(attn, nullptr, nullptr, out);
}